// round 16
// baseline (speedup 1.0000x reference)
#include <cuda_runtime.h>
#include <cuda_fp16.h>
#include <cstdint>

// Problem constants
#define BDIM 1024
#define LDIM 2
#define DDIM 1024
#define FDIM 32768
#define KENC 2048
#define NSPLIT 16
#define KSPLIT (FDIM / NSPLIT)          // 2048

// Tiling: CTA 128x128, 4 warps (2m x 2n), warp tile 64x64, BK=32 halves.
// STAGES=6, TWO k-tiles consumed per barrier (commit group = 2 stages).
#define STAGES 6
#define BK 32
#define THREADS 128
#define A_STAGE_BYTES (128 * BK * 2)    // 8192
#define B_STAGE_BYTES (BK * 128 * 2)    // 8192
#define STAGE_BYTES (A_STAGE_BYTES + B_STAGE_BYTES)
#define SMEM_DYN (STAGES * STAGE_BYTES) // 98304 ; 2 CTAs/SM = 192KB <= 228KB

// Scratch (device globals: allocation-guard safe)
__device__ __half g_fh [(size_t)BDIM * FDIM];          // 64 MB encoder output (fp16)
__device__ __half g_xh [(size_t)BDIM * KENC];          // 4 MB
__device__ __half g_weh[(size_t)KENC * FDIM];          // 128 MB
__device__ __half g_wdh[(size_t)LDIM * FDIM * DDIM];   // 128 MB (converted by enc's x==8 CTA column)
__device__ float  g_partial[(size_t)NSPLIT * BDIM * KENC]; // 128 MB split-K partials

// ---------------------------------------------------------------------------
// helpers
// ---------------------------------------------------------------------------
__device__ __forceinline__ uint32_t smem_u32(const void* p) {
    uint32_t a;
    asm("{ .reg .u64 t; cvta.to.shared.u64 t, %1; cvt.u32.u64 %0, t; }" : "=r"(a) : "l"(p));
    return a;
}

__device__ __forceinline__ void cp16(uint32_t dst, const void* src) {
    asm volatile("cp.async.cg.shared.global [%0], [%1], 16;" :: "r"(dst), "l"(src));
}

#define LDSM4(r, addr)                                                          \
    asm volatile("ldmatrix.sync.aligned.m8n8.x4.shared.b16 {%0,%1,%2,%3}, [%4];" \
        : "=r"((r)[0]), "=r"((r)[1]), "=r"((r)[2]), "=r"((r)[3]) : "r"(addr))

#define LDSM4T(r, addr)                                                         \
    asm volatile("ldmatrix.sync.aligned.m8n8.x4.trans.shared.b16 {%0,%1,%2,%3}, [%4];" \
        : "=r"((r)[0]), "=r"((r)[1]), "=r"((r)[2]), "=r"((r)[3]) : "r"(addr))

__device__ __forceinline__ void mma_f16(float c[4], const uint32_t a[4],
                                        const uint32_t b[2]) {
    asm volatile(
        "mma.sync.aligned.m16n8k16.row.col.f32.f16.f16.f32 "
        "{%0,%1,%2,%3}, {%4,%5,%6,%7}, {%8,%9}, {%0,%1,%2,%3};"
        : "+f"(c[0]), "+f"(c[1]), "+f"(c[2]), "+f"(c[3])
        : "r"(a[0]), "r"(a[1]), "r"(a[2]), "r"(a[3]), "r"(b[0]), "r"(b[1]));
}

__device__ __forceinline__ uint4 cvt8(float4 a, float4 b) {
    __half2 h0 = __float22half2_rn(make_float2(a.x, a.y));
    __half2 h1 = __float22half2_rn(make_float2(a.z, a.w));
    __half2 h2 = __float22half2_rn(make_float2(b.x, b.y));
    __half2 h3 = __float22half2_rn(make_float2(b.z, b.w));
    uint4 o;
    o.x = *reinterpret_cast<uint32_t*>(&h0);
    o.y = *reinterpret_cast<uint32_t*>(&h1);
    o.z = *reinterpret_cast<uint32_t*>(&h2);
    o.w = *reinterpret_cast<uint32_t*>(&h3);
    return o;
}

// ---------------------------------------------------------------------------
// fp32 -> fp16 convert (grid-stride, 8 elems/thread/iter)
// ---------------------------------------------------------------------------
__global__ void __launch_bounds__(256) cvt_kernel(
    const float* __restrict__ src, __half* __restrict__ dst, int n8)
{
    int stride = gridDim.x * blockDim.x;
    for (int i = blockIdx.x * blockDim.x + threadIdx.x; i < n8; i += stride) {
        float4 a = reinterpret_cast<const float4*>(src)[2 * i];
        float4 b = reinterpret_cast<const float4*>(src)[2 * i + 1];
        reinterpret_cast<uint4*>(dst)[i] = cvt8(a, b);
    }
}

// ---------------------------------------------------------------------------
// fp16 GEMM core: C[128,128] = A[128,K] (k-major) * B[K,128] (k-major rows)
// 4 warps (2m x 2n), warp tile 64x64, mma m16n8k16, ldmatrix operands.
// Mainloop consumes TWO k-tiles per wait_group/barrier (kTiles must be even).
// MODE 0: enc (fp32 bias + relu, __half output)
// MODE 1: dec (raw fp32 output)
// SMEM swizzles (conflict-free for cp.async writes AND all ldmatrix phases):
//   A[r][chunk c]  at r*64  + 16*(c  ^ ((r>>1)&3))     (4 chunks/row)
//   B[k][chunk nc] at k*256 + 16*(nc ^ (k&7))          (16 chunks/row)
// ---------------------------------------------------------------------------
template <int MODE>
__device__ __forceinline__ void gemm_f16(
    const __half* __restrict__ A, int lda,
    const __half* __restrict__ B, int ldb,
    void* __restrict__ Cv, int ldc,
    int kTiles, const float* __restrict__ bias)
{
    extern __shared__ char smem_raw[];
    const uint32_t base = smem_u32(smem_raw);

    const int tid  = threadIdx.x;
    const int lane = tid & 31;
    const int warp = tid >> 5;          // 0..3
    const int wm = (warp & 1) << 6;     // 0 / 64
    const int wn = (warp >> 1) << 6;    // 0 / 64
    const int ty = lane >> 2;
    const int tc = lane & 3;
    const int lr = lane & 7;
    const int g  = lane >> 3;           // ldmatrix lane group 0..3

    float acc[4][8][4];
#pragma unroll
    for (int mt = 0; mt < 4; mt++)
#pragma unroll
        for (int nt = 0; nt < 8; nt++)
#pragma unroll
            for (int i = 0; i < 4; i++) acc[mt][nt][i] = 0.f;

    // Loader precompute: 1024 16B-chunks/stage, 8 per thread. Pointers advance.
    uint32_t soff[8]; const __half* gp[8]; size_t gstep[8];
#pragma unroll
    for (int t = 0; t < 8; t++) {
        const int cid = tid + t * THREADS;
        if (cid < 512) {                       // A: [r 0..127][c 0..3]
            const int r = cid >> 2, c = cid & 3;
            soff[t]  = r * 64 + 16 * (c ^ ((r >> 1) & 3));
            gp[t]    = A + (size_t)r * lda + c * 8;
            gstep[t] = BK;
        } else {                               // B: [k 0..31][nc 0..15]
            const int b = cid - 512;
            const int k = b >> 4, nc = b & 15;
            soff[t]  = A_STAGE_BYTES + k * 256 + 16 * (nc ^ (k & 7));
            gp[t]    = B + (size_t)k * ldb + nc * 8;
            gstep[t] = (size_t)BK * ldb;
        }
    }

    // ldmatrix per-lane offsets (stage-relative), precomputed.
    uint32_t aoff[2][4], boff[2][4];
#pragma unroll
    for (int ks = 0; ks < 2; ks++) {
#pragma unroll
        for (int mt = 0; mt < 4; mt++) {
            const int row = wm + mt * 16 + lr + (g & 1) * 8;
            const int kc  = ks * 2 + (g >> 1);
            aoff[ks][mt] = row * 64 + 16 * (kc ^ ((row >> 1) & 3));
        }
#pragma unroll
        for (int np = 0; np < 4; np++) {
            const int k  = ks * 16 + lr + (g & 1) * 8;
            const int nc = (wn >> 3) + np * 2 + (g >> 1);
            boff[ks][np] = A_STAGE_BYTES + k * 256 + 16 * (nc ^ (k & 7));
        }
    }

    // Load one stage (no commit) and advance the global pointers.
#define LOAD_STAGE_NC(s)                                                        \
    do {                                                                        \
        const uint32_t sb_ = base + (s) * STAGE_BYTES;                          \
        _Pragma("unroll")                                                       \
        for (int t = 0; t < 8; t++) {                                           \
            cp16(sb_ + soff[t], gp[t]);                                         \
            gp[t] += gstep[t];                                                  \
        }                                                                       \
    } while (0)
#define COMMIT() asm volatile("cp.async.commit_group;")

    // Prologue: tiles 0..3 as 2 groups of 2 stages.
    LOAD_STAGE_NC(0); LOAD_STAGE_NC(1); COMMIT();
    LOAD_STAGE_NC(2); LOAD_STAGE_NC(3); COMMIT();

    int s = 0;   // stage of tile t0 = 2*it  (advances by 2 mod 6)
    const int iters = kTiles >> 1;
    for (int it = 0; it < iters; it++) {
        // Committed groups = 2 + it ; pending <= 1 => tiles 2it,2it+1 ready.
        asm volatile("cp.async.wait_group 1;");
        __syncthreads();

        // Refill tiles 2it+4, 2it+5 into stages (s+4)%6, (s+5)%6 — those
        // stages held tiles 2it-2, 2it-1, consumed last iteration (readers
        // finished before the barrier above). One commit group per refill.
        if (it + 2 < iters) {
            int r4 = s + 4; if (r4 >= STAGES) r4 -= STAGES;
            int r5 = s + 5; if (r5 >= STAGES) r5 -= STAGES;
            LOAD_STAGE_NC(r4); LOAD_STAGE_NC(r5); COMMIT();
        } else {
            COMMIT();
        }

        // Consume both tiles: 4 k-steps over stages s, s+1.
#pragma unroll
        for (int h = 0; h < 2; h++) {
            int sh = s + h; if (sh >= STAGES) sh -= STAGES;
            const uint32_t sb = base + sh * STAGE_BYTES;
#pragma unroll
            for (int ks = 0; ks < 2; ks++) {
                uint32_t af[4][4];
#pragma unroll
                for (int mt = 0; mt < 4; mt++) LDSM4(af[mt], sb + aoff[ks][mt]);
                uint32_t bf[8][2];
#pragma unroll
                for (int np = 0; np < 4; np++) {
                    uint32_t r[4];
                    LDSM4T(r, sb + boff[ks][np]);
                    bf[np * 2][0]     = r[0]; bf[np * 2][1]     = r[1];
                    bf[np * 2 + 1][0] = r[2]; bf[np * 2 + 1][1] = r[3];
                }
#pragma unroll
                for (int mt = 0; mt < 4; mt++)
#pragma unroll
                    for (int nt = 0; nt < 8; nt++)
                        mma_f16(acc[mt][nt], af[mt], bf[nt]);
            }
        }
        s += 2; if (s >= STAGES) s -= STAGES;
    }
#undef LOAD_STAGE_NC
#undef COMMIT

    // Epilogue. acc layout: c0,c1 -> (row ty, n 2tc,2tc+1); c2,c3 -> row ty+8.
#pragma unroll
    for (int mt = 0; mt < 4; mt++) {
#pragma unroll
        for (int nt = 0; nt < 8; nt++) {
            const int r = wm + mt * 16 + ty;
            const int c = wn + nt * 8 + tc * 2;
            float v0 = acc[mt][nt][0], v1 = acc[mt][nt][1];
            float v2 = acc[mt][nt][2], v3 = acc[mt][nt][3];
            if (MODE == 0) {
                const float b0 = bias[c], b1 = bias[c + 1];
                v0 = fmaxf(v0 + b0, 0.f); v1 = fmaxf(v1 + b1, 0.f);
                v2 = fmaxf(v2 + b0, 0.f); v3 = fmaxf(v3 + b1, 0.f);
                __half* C = (__half*)Cv;
                *(__half2*)(C + (size_t)r * ldc + c) =
                    __float22half2_rn(make_float2(v0, v1));
                *(__half2*)(C + (size_t)(r + 8) * ldc + c) =
                    __float22half2_rn(make_float2(v2, v3));
            } else {
                float* C = (float*)Cv;
                *(float2*)(C + (size_t)r * ldc + c)       = make_float2(v0, v1);
                *(float2*)(C + (size_t)(r + 8) * ldc + c) = make_float2(v2, v3);
            }
        }
    }
}

// ---------------------------------------------------------------------------
// Encoder: f = relu(x @ W_enc + b_enc) -> fp16. grid (9 m-fastest, 256 n).
//   x < 8 : GEMM tile (m = x).
//   x == 8: W_dec fp32->fp16 streaming conversion (dependency-free vs enc,
//           soaks up enc's idle DRAM bandwidth).
// ---------------------------------------------------------------------------
__global__ void __launch_bounds__(THREADS, 2) enc_kernel(
    const float* __restrict__ benc, const float* __restrict__ Wdec)
{
    if (blockIdx.x == 8) {
        // 8,388,608 uint4 units total; 256 CTAs x 128 threads x 256 units.
        const float4* src = reinterpret_cast<const float4*>(Wdec);
        uint4* dst = reinterpret_cast<uint4*>(g_wdh);
        const int u0 = blockIdx.y * 32768 + threadIdx.x;
#pragma unroll 4
        for (int t = 0; t < 256; t++) {
            const int u = u0 + t * THREADS;
            const float4 a = src[2 * u];
            const float4 b = src[2 * u + 1];
            dst[u] = cvt8(a, b);
        }
        return;
    }
    const int m = blockIdx.x, n = blockIdx.y;
    gemm_f16<0>(g_xh + (size_t)m * 128 * KENC, KENC,
                g_weh + (size_t)n * 128, FDIM,
                g_fh + (size_t)m * 128 * FDIM + (size_t)n * 128, FDIM,
                KENC / BK, benc + n * 128);
}

// ---------------------------------------------------------------------------
// Decoder split-K: partial[s] += f[:, sK:(s+1)K] @ W_dec. grid (8 m, 16 n, 16 s)
// n tile: l = n>>3, d-block = n&7 (128-wide tiles never straddle l)
// ---------------------------------------------------------------------------
__global__ void __launch_bounds__(THREADS, 2) dec_kernel()
{
    const int m = blockIdx.x, n = blockIdx.y, split = blockIdx.z;
    const int l = n >> 3, db = n & 7;
    gemm_f16<1>(g_fh + (size_t)m * 128 * FDIM + (size_t)split * KSPLIT, FDIM,
                g_wdh + (size_t)l * FDIM * DDIM + (size_t)split * KSPLIT * DDIM
                      + (size_t)db * 128, DDIM,
                g_partial + (size_t)split * BDIM * KENC
                          + (size_t)m * 128 * KENC + (size_t)n * 128, KENC,
                KSPLIT / BK, nullptr);
}

// ---------------------------------------------------------------------------
// Reduce: out[b, n] = b_dec[n] + sum_s partial[s][b][n]   (separate launch —
// fusing it into dec was measured 88us slower in R14)
// ---------------------------------------------------------------------------
__global__ void __launch_bounds__(256) reduce_kernel(
    const float* __restrict__ bdec, float* __restrict__ out)
{
    const int i = blockIdx.x * blockDim.x + threadIdx.x;  // float4 index
    float4 s = reinterpret_cast<const float4*>(bdec)[i & 511];
#pragma unroll
    for (int p = 0; p < NSPLIT; p++) {
        float4 v = reinterpret_cast<const float4*>(g_partial)[(size_t)p * 524288 + i];
        s.x += v.x; s.y += v.y; s.z += v.z; s.w += v.w;
    }
    reinterpret_cast<float4*>(out)[i] = s;
}

// ---------------------------------------------------------------------------
extern "C" void kernel_launch(void* const* d_in, const int* in_sizes, int n_in,
                              void* d_out, int out_size)
{
    const float* x    = (const float*)d_in[0];   // [1024, 2, 1024]
    const float* Wenc = (const float*)d_in[1];   // [2, 1024, 32768]
    const float* benc = (const float*)d_in[2];   // [32768]
    const float* Wdec = (const float*)d_in[3];   // [2, 32768, 1024]
    const float* bdec = (const float*)d_in[4];   // [2, 1024]
    float* out = (float*)d_out;                  // [1024, 2, 1024]

    __half* gx; __half* gwe;
    cudaGetSymbolAddress((void**)&gx,  g_xh);
    cudaGetSymbolAddress((void**)&gwe, g_weh);

    cudaFuncSetAttribute(enc_kernel, cudaFuncAttributeMaxDynamicSharedMemorySize, SMEM_DYN);
    cudaFuncSetAttribute(dec_kernel, cudaFuncAttributeMaxDynamicSharedMemorySize, SMEM_DYN);

    // fp32 -> fp16 (RN): x and W_enc up front; W_dec converts inside enc's
    // extra CTA column, overlapped with the encoder GEMM.
    cvt_kernel<<<512,  256>>>(x,    gx,  (BDIM * KENC) / 8);
    cvt_kernel<<<2048, 256>>>(Wenc, gwe, (KENC * FDIM) / 8);

    enc_kernel<<<dim3(9, FDIM / 128), THREADS, SMEM_DYN>>>(benc, Wdec);
    dec_kernel<<<dim3(BDIM / 128, KENC / 128, NSPLIT), THREADS, SMEM_DYN>>>();
    reduce_kernel<<<(BDIM * KENC / 4) / 256, 256>>>(bdec, out);
}

// round 17
// speedup vs baseline: 1.0785x; 1.0785x over previous
#include <cuda_runtime.h>
#include <cuda_fp16.h>
#include <cstdint>

// Problem constants
#define BDIM 1024
#define LDIM 2
#define DDIM 1024
#define FDIM 32768
#define KENC 2048
#define NSPLIT 16
#define KSPLIT (FDIM / NSPLIT)          // 2048

// Tiling: CTA 128x128, 4 warps (2m x 2n), warp tile 64x64, BK=32 halves
// (exact R12 configuration — verified best; R9/R11/R15/R16 perturbations all lost)
#define STAGES 4
#define BK 32
#define THREADS 128
#define A_STAGE_BYTES (128 * BK * 2)    // 8192
#define B_STAGE_BYTES (BK * 128 * 2)    // 8192
#define STAGE_BYTES (A_STAGE_BYTES + B_STAGE_BYTES)
#define SMEM_DYN (STAGES * STAGE_BYTES) // 65536

// Scratch (device globals: allocation-guard safe)
__device__ __half g_fh [(size_t)BDIM * FDIM];          // 64 MB encoder output (fp16)
__device__ __half g_xh [(size_t)BDIM * KENC];          // 4 MB
__device__ __half g_weh[(size_t)KENC * FDIM];          // 128 MB
__device__ __half g_wdh[(size_t)LDIM * FDIM * DDIM];   // 128 MB (converted by enc's x==8 CTA column)
__device__ __half g_parth[(size_t)NSPLIT * BDIM * KENC]; // 64 MB fp16 split-K partials

// ---------------------------------------------------------------------------
// helpers
// ---------------------------------------------------------------------------
__device__ __forceinline__ uint32_t smem_u32(const void* p) {
    uint32_t a;
    asm("{ .reg .u64 t; cvta.to.shared.u64 t, %1; cvt.u32.u64 %0, t; }" : "=r"(a) : "l"(p));
    return a;
}

__device__ __forceinline__ void cp16(uint32_t dst, const void* src) {
    asm volatile("cp.async.cg.shared.global [%0], [%1], 16;" :: "r"(dst), "l"(src));
}

#define LDSM4(r, addr)                                                          \
    asm volatile("ldmatrix.sync.aligned.m8n8.x4.shared.b16 {%0,%1,%2,%3}, [%4];" \
        : "=r"((r)[0]), "=r"((r)[1]), "=r"((r)[2]), "=r"((r)[3]) : "r"(addr))

#define LDSM4T(r, addr)                                                         \
    asm volatile("ldmatrix.sync.aligned.m8n8.x4.trans.shared.b16 {%0,%1,%2,%3}, [%4];" \
        : "=r"((r)[0]), "=r"((r)[1]), "=r"((r)[2]), "=r"((r)[3]) : "r"(addr))

__device__ __forceinline__ void mma_f16(float c[4], const uint32_t a[4],
                                        const uint32_t b[2]) {
    asm volatile(
        "mma.sync.aligned.m16n8k16.row.col.f32.f16.f16.f32 "
        "{%0,%1,%2,%3}, {%4,%5,%6,%7}, {%8,%9}, {%0,%1,%2,%3};"
        : "+f"(c[0]), "+f"(c[1]), "+f"(c[2]), "+f"(c[3])
        : "r"(a[0]), "r"(a[1]), "r"(a[2]), "r"(a[3]), "r"(b[0]), "r"(b[1]));
}

__device__ __forceinline__ uint4 cvt8(float4 a, float4 b) {
    __half2 h0 = __float22half2_rn(make_float2(a.x, a.y));
    __half2 h1 = __float22half2_rn(make_float2(a.z, a.w));
    __half2 h2 = __float22half2_rn(make_float2(b.x, b.y));
    __half2 h3 = __float22half2_rn(make_float2(b.z, b.w));
    uint4 o;
    o.x = *reinterpret_cast<uint32_t*>(&h0);
    o.y = *reinterpret_cast<uint32_t*>(&h1);
    o.z = *reinterpret_cast<uint32_t*>(&h2);
    o.w = *reinterpret_cast<uint32_t*>(&h3);
    return o;
}

// ---------------------------------------------------------------------------
// fp32 -> fp16 convert (grid-stride, 8 elems/thread/iter)
// ---------------------------------------------------------------------------
__global__ void __launch_bounds__(256) cvt_kernel(
    const float* __restrict__ src, __half* __restrict__ dst, int n8)
{
    int stride = gridDim.x * blockDim.x;
    for (int i = blockIdx.x * blockDim.x + threadIdx.x; i < n8; i += stride) {
        float4 a = reinterpret_cast<const float4*>(src)[2 * i];
        float4 b = reinterpret_cast<const float4*>(src)[2 * i + 1];
        reinterpret_cast<uint4*>(dst)[i] = cvt8(a, b);
    }
}

// ---------------------------------------------------------------------------
// fp16 GEMM core: C[128,128] = A[128,K] (k-major) * B[K,128] (k-major rows)
// 4 warps (2m x 2n), warp tile 64x64, mma m16n8k16, ldmatrix operands.
// MODE 0: enc (fp32 bias + relu, __half output)
// MODE 1: dec (raw __half output -- fp16 split-K partials)
// SMEM swizzles (conflict-free for cp.async writes AND all ldmatrix phases):
//   A[r][chunk c]  at r*64  + 16*(c  ^ ((r>>1)&3))     (4 chunks/row)
//   B[k][chunk nc] at k*256 + 16*(nc ^ (k&7))          (16 chunks/row)
// ---------------------------------------------------------------------------
template <int MODE>
__device__ __forceinline__ void gemm_f16(
    const __half* __restrict__ A, int lda,
    const __half* __restrict__ B, int ldb,
    __half* __restrict__ C, int ldc,
    int kTiles, const float* __restrict__ bias)
{
    extern __shared__ char smem_raw[];
    const uint32_t base = smem_u32(smem_raw);

    const int tid  = threadIdx.x;
    const int lane = tid & 31;
    const int warp = tid >> 5;          // 0..3
    const int wm = (warp & 1) << 6;     // 0 / 64
    const int wn = (warp >> 1) << 6;    // 0 / 64
    const int ty = lane >> 2;
    const int tc = lane & 3;
    const int lr = lane & 7;
    const int g  = lane >> 3;           // ldmatrix lane group 0..3

    float acc[4][8][4];
#pragma unroll
    for (int mt = 0; mt < 4; mt++)
#pragma unroll
        for (int nt = 0; nt < 8; nt++)
#pragma unroll
            for (int i = 0; i < 4; i++) acc[mt][nt][i] = 0.f;

    // Loader precompute: 1024 16B-chunks/stage, 8 per thread. Pointers advance.
    uint32_t soff[8]; const __half* gp[8]; size_t gstep[8];
#pragma unroll
    for (int t = 0; t < 8; t++) {
        const int cid = tid + t * THREADS;
        if (cid < 512) {                       // A: [r 0..127][c 0..3]
            const int r = cid >> 2, c = cid & 3;
            soff[t]  = r * 64 + 16 * (c ^ ((r >> 1) & 3));
            gp[t]    = A + (size_t)r * lda + c * 8;
            gstep[t] = BK;
        } else {                               // B: [k 0..31][nc 0..15]
            const int b = cid - 512;
            const int k = b >> 4, nc = b & 15;
            soff[t]  = A_STAGE_BYTES + k * 256 + 16 * (nc ^ (k & 7));
            gp[t]    = B + (size_t)k * ldb + nc * 8;
            gstep[t] = (size_t)BK * ldb;
        }
    }

    // ldmatrix per-lane offsets (stage-relative), precomputed.
    uint32_t aoff[2][4], boff[2][4];
#pragma unroll
    for (int ks = 0; ks < 2; ks++) {
#pragma unroll
        for (int mt = 0; mt < 4; mt++) {
            const int row = wm + mt * 16 + lr + (g & 1) * 8;
            const int kc  = ks * 2 + (g >> 1);
            aoff[ks][mt] = row * 64 + 16 * (kc ^ ((row >> 1) & 3));
        }
#pragma unroll
        for (int np = 0; np < 4; np++) {
            const int k  = ks * 16 + lr + (g & 1) * 8;
            const int nc = (wn >> 3) + np * 2 + (g >> 1);
            boff[ks][np] = A_STAGE_BYTES + k * 256 + 16 * (nc ^ (k & 7));
        }
    }

#define LOAD_STAGE(s)                                                           \
    do {                                                                        \
        const uint32_t sb_ = base + (s) * STAGE_BYTES;                          \
        _Pragma("unroll")                                                       \
        for (int t = 0; t < 8; t++) {                                           \
            cp16(sb_ + soff[t], gp[t]);                                         \
            gp[t] += gstep[t];                                                  \
        }                                                                       \
        asm volatile("cp.async.commit_group;");                                 \
    } while (0)

    // Prologue: fill STAGES-1 = 3 stages
#pragma unroll
    for (int p = 0; p < STAGES - 1; p++) LOAD_STAGE(p);

    for (int kt = 0; kt < kTiles; kt++) {
        asm volatile("cp.async.wait_group %0;" :: "n"(STAGES - 2));
        __syncthreads();

        // Refill stage (kt-1)&3 — its readers finished before the barrier.
        if (kt + STAGES - 1 < kTiles) {
            LOAD_STAGE((kt + STAGES - 1) & (STAGES - 1));
        } else {
            asm volatile("cp.async.commit_group;");
        }

        const uint32_t sb = base + (kt & (STAGES - 1)) * STAGE_BYTES;
#pragma unroll
        for (int ks = 0; ks < 2; ks++) {
            uint32_t af[4][4];
#pragma unroll
            for (int mt = 0; mt < 4; mt++) LDSM4(af[mt], sb + aoff[ks][mt]);
            uint32_t bf[8][2];
#pragma unroll
            for (int np = 0; np < 4; np++) {
                uint32_t r[4];
                LDSM4T(r, sb + boff[ks][np]);
                bf[np * 2][0]     = r[0]; bf[np * 2][1]     = r[1];
                bf[np * 2 + 1][0] = r[2]; bf[np * 2 + 1][1] = r[3];
            }
#pragma unroll
            for (int mt = 0; mt < 4; mt++)
#pragma unroll
                for (int nt = 0; nt < 8; nt++)
                    mma_f16(acc[mt][nt], af[mt], bf[nt]);
        }
    }
#undef LOAD_STAGE

    // Epilogue (fp16 out for both modes).
    // acc layout: c0,c1 -> (row ty, n 2tc,2tc+1); c2,c3 -> row ty+8.
#pragma unroll
    for (int mt = 0; mt < 4; mt++) {
#pragma unroll
        for (int nt = 0; nt < 8; nt++) {
            const int r = wm + mt * 16 + ty;
            const int c = wn + nt * 8 + tc * 2;
            float v0 = acc[mt][nt][0], v1 = acc[mt][nt][1];
            float v2 = acc[mt][nt][2], v3 = acc[mt][nt][3];
            if (MODE == 0) {
                const float b0 = bias[c], b1 = bias[c + 1];
                v0 = fmaxf(v0 + b0, 0.f); v1 = fmaxf(v1 + b1, 0.f);
                v2 = fmaxf(v2 + b0, 0.f); v3 = fmaxf(v3 + b1, 0.f);
            }
            *(__half2*)(C + (size_t)r * ldc + c) =
                __float22half2_rn(make_float2(v0, v1));
            *(__half2*)(C + (size_t)(r + 8) * ldc + c) =
                __float22half2_rn(make_float2(v2, v3));
        }
    }
}

// ---------------------------------------------------------------------------
// Encoder: f = relu(x @ W_enc + b_enc) -> fp16. grid (9 m-fastest, 256 n).
//   x < 8 : GEMM tile (m = x).
//   x == 8: W_dec fp32->fp16 streaming conversion (dependency-free vs enc,
//           soaks up enc's idle DRAM bandwidth).
// ---------------------------------------------------------------------------
__global__ void __launch_bounds__(THREADS, 2) enc_kernel(
    const float* __restrict__ benc, const float* __restrict__ Wdec)
{
    if (blockIdx.x == 8) {
        // 8,388,608 uint4 units total; 256 CTAs x 128 threads x 256 units.
        const float4* src = reinterpret_cast<const float4*>(Wdec);
        uint4* dst = reinterpret_cast<uint4*>(g_wdh);
        const int u0 = blockIdx.y * 32768 + threadIdx.x;
#pragma unroll 4
        for (int t = 0; t < 256; t++) {
            const int u = u0 + t * THREADS;
            const float4 a = src[2 * u];
            const float4 b = src[2 * u + 1];
            dst[u] = cvt8(a, b);
        }
        return;
    }
    const int m = blockIdx.x, n = blockIdx.y;
    gemm_f16<0>(g_xh + (size_t)m * 128 * KENC, KENC,
                g_weh + (size_t)n * 128, FDIM,
                g_fh + (size_t)m * 128 * FDIM + (size_t)n * 128, FDIM,
                KENC / BK, benc + n * 128);
}

// ---------------------------------------------------------------------------
// Decoder split-K: parth[s] = f[:, sK:(s+1)K] @ W_dec  (fp16 partials).
// grid (8 m, 16 n, 16 s). n tile: l = n>>3, d-block = n&7.
// ---------------------------------------------------------------------------
__global__ void __launch_bounds__(THREADS, 2) dec_kernel()
{
    const int m = blockIdx.x, n = blockIdx.y, split = blockIdx.z;
    const int l = n >> 3, db = n & 7;
    gemm_f16<1>(g_fh + (size_t)m * 128 * FDIM + (size_t)split * KSPLIT, FDIM,
                g_wdh + (size_t)l * FDIM * DDIM + (size_t)split * KSPLIT * DDIM
                      + (size_t)db * 128, DDIM,
                g_parth + (size_t)split * BDIM * KENC
                        + (size_t)m * 128 * KENC + (size_t)n * 128, KENC,
                KSPLIT / BK, nullptr);
}

// ---------------------------------------------------------------------------
// Reduce: out[b, n] = b_dec[n] + sum_s parth[s][b][n]  (fp16 partials, fixed
// order -> deterministic; separate launch — fusing measured 88us slower R14)
// ---------------------------------------------------------------------------
__global__ void __launch_bounds__(256) reduce_kernel(
    const float* __restrict__ bdec, float* __restrict__ out)
{
    const int i = blockIdx.x * blockDim.x + threadIdx.x;  // float4 index (x4 elems)
    float4 s = reinterpret_cast<const float4*>(bdec)[i & 511];
    const uint2* pp = reinterpret_cast<const uint2*>(g_parth);   // 4 halves / uint2
#pragma unroll
    for (int p = 0; p < NSPLIT; p++) {
        uint2 hv = pp[(size_t)p * 524288 + i];
        __half2 h0 = *reinterpret_cast<__half2*>(&hv.x);
        __half2 h1 = *reinterpret_cast<__half2*>(&hv.y);
        float2 f0 = __half22float2(h0);
        float2 f1 = __half22float2(h1);
        s.x += f0.x; s.y += f0.y; s.z += f1.x; s.w += f1.y;
    }
    reinterpret_cast<float4*>(out)[i] = s;
}

// ---------------------------------------------------------------------------
extern "C" void kernel_launch(void* const* d_in, const int* in_sizes, int n_in,
                              void* d_out, int out_size)
{
    const float* x    = (const float*)d_in[0];   // [1024, 2, 1024]
    const float* Wenc = (const float*)d_in[1];   // [2, 1024, 32768]
    const float* benc = (const float*)d_in[2];   // [32768]
    const float* Wdec = (const float*)d_in[3];   // [2, 32768, 1024]
    const float* bdec = (const float*)d_in[4];   // [2, 1024]
    float* out = (float*)d_out;                  // [1024, 2, 1024]

    __half* gx; __half* gwe;
    cudaGetSymbolAddress((void**)&gx,  g_xh);
    cudaGetSymbolAddress((void**)&gwe, g_weh);

    cudaFuncSetAttribute(enc_kernel, cudaFuncAttributeMaxDynamicSharedMemorySize, SMEM_DYN);
    cudaFuncSetAttribute(dec_kernel, cudaFuncAttributeMaxDynamicSharedMemorySize, SMEM_DYN);

    // fp32 -> fp16 (RN): x and W_enc up front; W_dec converts inside enc's
    // extra CTA column, overlapped with the encoder GEMM.
    cvt_kernel<<<512,  256>>>(x,    gx,  (BDIM * KENC) / 8);
    cvt_kernel<<<2048, 256>>>(Wenc, gwe, (KENC * FDIM) / 8);

    enc_kernel<<<dim3(9, FDIM / 128), THREADS, SMEM_DYN>>>(benc, Wdec);
    dec_kernel<<<dim3(BDIM / 128, KENC / 128, NSPLIT), THREADS, SMEM_DYN>>>();
    reduce_kernel<<<(BDIM * KENC / 4) / 256, 256>>>(bdec, out);
}